// round 13
// baseline (speedup 1.0000x reference)
#include <cuda_runtime.h>
#include <cuda_fp16.h>
#include <cstdint>

#define NN 50000
#define EE 1600000
#define RR 50
#define BB 30
#define HH 16
#define CC 4
#define NH  (NN * HH)
#define NH4 (NN * HH / 4)
#define RCH 25              // relations per w1 y-slice
#define RPAD 28             // padded r-stride for LDS.128 coef loads
#define NBLKN 196           // ceil(NN/256)

// ---------------- scratch (device globals; no allocation) ----------------
__device__ uint4  g_w1h[(size_t)RR * NN * 2];      // [R,N,H] fp16: 32B/row, 80MB
__device__ float4 g_w2[RR * HH];                   // [R,H,C] fp32
__device__ uint4  g_xsumh[NN * 2];                 // layer1 sums, fp16 (plain ST now)
__device__ float4 g_x[NN * HH / 4];                // relu'd hidden (fp32, for k_out)
__device__ uint4  g_xh[NN * 2];                    // relu'd hidden (fp16, edge2 gather)
__device__ float  g_cnt[NN];                       // in-degree (float)
__device__ float4 g_osum[NN];                      // layer2 sums (plain ST now)
// edge grouping
__device__ int          g_degI[NN];
__device__ int          g_nodebase[NN];
__device__ int          g_cursorI[NN];
__device__ int          g_alloc;
__device__ unsigned int g_se[EE];                  // packed s | (t<<16), grouped by dst

__device__ __forceinline__ void fma4(float4& a, float s, float4 w) {
    a.x += s * w.x; a.y += s * w.y; a.z += s * w.z; a.w += s * w.w;
}
__device__ __forceinline__ unsigned int h2bits(__half2 h) { return *(unsigned int*)&h; }
__device__ __forceinline__ __half2 bits2h(unsigned int u) { return *(__half2*)&u; }

// ---------------- D0: zero degree counters ----------------
__global__ void k_d0() {
    int i = blockIdx.x * blockDim.x + threadIdx.x;
    if (i < NN) g_degI[i] = 0;
    if (i == 0) g_alloc = 0;
}

// ---------------- D1: count in-degrees ----------------
__global__ void k_d1(const int* __restrict__ ei) {
    int e = blockIdx.x * blockDim.x + threadIdx.x;
    if (e < EE) atomicAdd(&g_degI[ei[EE + e]], 1);
}

// ---------------- D2: allocate per-node segments (block scan + 1 atomic/block) ----------------
__global__ void k_d2() {
    __shared__ int sc[256];
    __shared__ int bb;
    int tid = threadIdx.x;
    int i = blockIdx.x * 256 + tid;
    int v = (i < NN) ? g_degI[i] : 0;
    sc[tid] = v;
    __syncthreads();
    int inc = v;
    #pragma unroll
    for (int o = 1; o < 256; o <<= 1) {
        int t = (tid >= o) ? sc[tid - o] : 0;
        __syncthreads();
        inc += t;
        sc[tid] = inc;
        __syncthreads();
    }
    if (tid == 255) bb = atomicAdd(&g_alloc, sc[255]);
    __syncthreads();
    int base = bb + inc - v;
    if (i < NN) {
        g_nodebase[i] = base;
        g_cursorI[i]  = base;
        g_cnt[i]      = (float)v;
    }
}

// ---------------- D3: scatter packed (s, t) records into dst segments ----------------
__global__ void k_d3(const int* __restrict__ ei, const int* __restrict__ et) {
    int e = blockIdx.x * blockDim.x + threadIdx.x;
    if (e >= EE) return;
    int s = ei[e];
    int d = ei[EE + e];
    int t = et[e];
    int pos = atomicAdd(&g_cursorI[d], 1);
    g_se[pos] = (unsigned int)s | ((unsigned int)t << 16);
}

// ---------------- K1: w1 slice (grid (1563,2)) ----------------
__global__ void __launch_bounds__(128) k_w1(const float4* __restrict__ basis1,
                                            const float* __restrict__ comp1) {
    int r0 = blockIdx.y * RCH;
    __shared__ __align__(16) unsigned int schv[BB * RPAD];  // [b][r] half2(c,c)
    for (int i = threadIdx.x; i < BB * RPAD; i += blockDim.x) {
        int b = i / RPAD, r = i - b * RPAD;
        float c = (r < RCH) ? comp1[(r0 + r) * BB + b] : 0.f;
        schv[i] = h2bits(__floats2half2_rn(c, c));
    }
    __syncthreads();

    int i4 = blockIdx.x * blockDim.x + threadIdx.x;
    if (i4 >= NH4) return;

    __half2 a0[RCH], a1[RCH];
    const __half2 hz = __floats2half2_rn(0.f, 0.f);
    #pragma unroll
    for (int r = 0; r < RCH; r++) { a0[r] = hz; a1[r] = hz; }

    float4 v = basis1[i4];
    #pragma unroll 1
    for (int b = 0; b < BB; b++) {
        float4 vn = make_float4(0.f, 0.f, 0.f, 0.f);
        if (b + 1 < BB) vn = basis1[(size_t)(b + 1) * NH4 + i4];

        __half2 lo = __floats2half2_rn(v.x, v.y);
        __half2 hi = __floats2half2_rn(v.z, v.w);
        const unsigned int* cb = &schv[b * RPAD];

        #pragma unroll
        for (int rg = 0; rg < 6; rg++) {
            uint4 c4 = *(const uint4*)(cb + rg * 4);
            int r = rg * 4;
            a0[r+0] = __hfma2(bits2h(c4.x), lo, a0[r+0]);
            a1[r+0] = __hfma2(bits2h(c4.x), hi, a1[r+0]);
            a0[r+1] = __hfma2(bits2h(c4.y), lo, a0[r+1]);
            a1[r+1] = __hfma2(bits2h(c4.y), hi, a1[r+1]);
            a0[r+2] = __hfma2(bits2h(c4.z), lo, a0[r+2]);
            a1[r+2] = __hfma2(bits2h(c4.z), hi, a1[r+2]);
            a0[r+3] = __hfma2(bits2h(c4.w), lo, a0[r+3]);
            a1[r+3] = __hfma2(bits2h(c4.w), hi, a1[r+3]);
        }
        {
            __half2 cc = bits2h(cb[24]);
            a0[24] = __hfma2(cc, lo, a0[24]);
            a1[24] = __hfma2(cc, hi, a1[24]);
        }
        v = vn;
    }

    int n = i4 >> 2;
    int q = i4 & 3;
    uint2* outp = (uint2*)g_w1h;
    #pragma unroll
    for (int r = 0; r < RCH; r++) {
        uint2 o;
        o.x = h2bits(a0[r]);
        o.y = h2bits(a1[r]);
        outp[(((size_t)(r0 + r) * NN + n) << 2) + q] = o;
    }
}

// ---------------- K2: layer-1, one warp per dst node (NO atomics) ----------------
__global__ void k_edge1n() {
    int gw = (blockIdx.x * blockDim.x + threadIdx.x) >> 5;
    int lane = threadIdx.x & 31;
    if (gw >= NN) return;
    int start = g_nodebase[gw];
    int deg   = g_degI[gw];

    __half2 a[8];
    const __half2 hz = __floats2half2_rn(0.f, 0.f);
    #pragma unroll
    for (int j = 0; j < 8; j++) a[j] = hz;

    for (int i = start + lane; i < start + deg; i += 32) {
        unsigned int p = g_se[i];
        int s = p & 0xFFFF;
        int t = p >> 16;
        const uint4* row = g_w1h + ((size_t)t * NN + s) * 2;
        uint4 u = row[0];
        uint4 w = row[1];
        a[0] = __hadd2(a[0], bits2h(u.x));
        a[1] = __hadd2(a[1], bits2h(u.y));
        a[2] = __hadd2(a[2], bits2h(u.z));
        a[3] = __hadd2(a[3], bits2h(u.w));
        a[4] = __hadd2(a[4], bits2h(w.x));
        a[5] = __hadd2(a[5], bits2h(w.y));
        a[6] = __hadd2(a[6], bits2h(w.z));
        a[7] = __hadd2(a[7], bits2h(w.w));
    }

    #pragma unroll
    for (int o = 16; o > 0; o >>= 1) {
        #pragma unroll
        for (int j = 0; j < 8; j++)
            a[j] = __hadd2(a[j], bits2h(__shfl_xor_sync(0xffffffffu, h2bits(a[j]), o)));
    }

    if (lane == 0) {
        g_xsumh[gw * 2]     = make_uint4(h2bits(a[0]), h2bits(a[1]), h2bits(a[2]), h2bits(a[3]));
        g_xsumh[gw * 2 + 1] = make_uint4(h2bits(a[4]), h2bits(a[5]), h2bits(a[6]), h2bits(a[7]));
    }
}

// ---------------- K3: x = relu(mean + root1 + bias1), plus w2 build ----------------
__global__ void k_x_w2(const float4* __restrict__ root1, const float4* __restrict__ bias1,
                       const float* __restrict__ comp2, const float* __restrict__ basis2) {
    if (blockIdx.x == NBLKN) {
        __shared__ float sc[RR * BB];
        __shared__ float sb[BB * HH * CC];
        for (int i = threadIdx.x; i < RR * BB; i += blockDim.x) sc[i] = comp2[i];
        for (int i = threadIdx.x; i < BB * HH * CC; i += blockDim.x) sb[i] = basis2[i];
        __syncthreads();
        float* w2f = (float*)g_w2;
        for (int i = threadIdx.x; i < RR * HH * CC; i += blockDim.x) {
            int r = i / (HH * CC);
            int hc = i % (HH * CC);
            float acc = 0.f;
            #pragma unroll
            for (int b = 0; b < BB; b++) acc += sc[r * BB + b] * sb[b * HH * CC + hc];
            w2f[i] = acc;
        }
        return;
    }

    int n = blockIdx.x * blockDim.x + threadIdx.x;
    if (n >= NN) return;
    float inv = 1.f / fmaxf(g_cnt[n], 1.f);
    uint4 a = g_xsumh[n * 2];
    uint4 b = g_xsumh[n * 2 + 1];
    unsigned int w[8] = {a.x, a.y, a.z, a.w, b.x, b.y, b.z, b.w};
    unsigned int hx[8];
    #pragma unroll
    for (int j = 0; j < 4; j++) {
        float2 lo = __half22float2(bits2h(w[j * 2]));
        float2 hi = __half22float2(bits2h(w[j * 2 + 1]));
        float4 rv = root1[n * 4 + j];
        float4 bv = bias1[j];
        float4 o;
        o.x = fmaxf(lo.x * inv + rv.x + bv.x, 0.f);
        o.y = fmaxf(lo.y * inv + rv.y + bv.y, 0.f);
        o.z = fmaxf(hi.x * inv + rv.z + bv.z, 0.f);
        o.w = fmaxf(hi.y * inv + rv.w + bv.w, 0.f);
        g_x[n * 4 + j] = o;
        hx[j * 2]     = h2bits(__floats2half2_rn(o.x, o.y));
        hx[j * 2 + 1] = h2bits(__floats2half2_rn(o.z, o.w));
    }
    g_xh[n * 2]     = make_uint4(hx[0], hx[1], hx[2], hx[3]);
    g_xh[n * 2 + 1] = make_uint4(hx[4], hx[5], hx[6], hx[7]);
}

// ---------------- K4: layer-2, one warp per dst node (NO atomics) ----------------
__global__ void k_edge2n() {
    __shared__ unsigned long long sw2h[HH * 64];  // 8 KB, [h*64 + t] half4
    for (int i = threadIdx.x; i < RR * HH; i += blockDim.x) {
        int r = i / HH, h = i % HH;
        float4 w = g_w2[r * HH + h];
        uint2 p;
        p.x = h2bits(__floats2half2_rn(w.x, w.y));
        p.y = h2bits(__floats2half2_rn(w.z, w.w));
        sw2h[h * 64 + r] = *(unsigned long long*)&p;
    }
    __syncthreads();

    int gw = (blockIdx.x * blockDim.x + threadIdx.x) >> 5;
    int lane = threadIdx.x & 31;
    if (gw >= NN) return;
    int start = g_nodebase[gw];
    int deg   = g_degI[gw];

    float4 acc = make_float4(0.f, 0.f, 0.f, 0.f);

    for (int i = start + lane; i < start + deg; i += 32) {
        unsigned int p = g_se[i];
        int s = p & 0xFFFF;
        int t = p >> 16;

        uint4 xa = g_xh[s * 2];
        uint4 xb = g_xh[s * 2 + 1];
        unsigned int xw[8] = {xa.x, xa.y, xa.z, xa.w, xb.x, xb.y, xb.z, xb.w};
        float xf[16];
        #pragma unroll
        for (int j = 0; j < 8; j++) {
            float2 f = __half22float2(bits2h(xw[j]));
            xf[j * 2] = f.x;
            xf[j * 2 + 1] = f.y;
        }
        #pragma unroll
        for (int h = 0; h < HH; h++) {
            unsigned long long wp = sw2h[h * 64 + t];
            uint2 q = *(uint2*)&wp;
            float2 wlo = __half22float2(bits2h(q.x));
            float2 whi = __half22float2(bits2h(q.y));
            fma4(acc, xf[h], make_float4(wlo.x, wlo.y, whi.x, whi.y));
        }
    }

    #pragma unroll
    for (int o = 16; o > 0; o >>= 1) {
        acc.x += __shfl_xor_sync(0xffffffffu, acc.x, o);
        acc.y += __shfl_xor_sync(0xffffffffu, acc.y, o);
        acc.z += __shfl_xor_sync(0xffffffffu, acc.z, o);
        acc.w += __shfl_xor_sync(0xffffffffu, acc.w, o);
    }

    if (lane == 0) g_osum[gw] = acc;
}

// ---------------- K5: out = log_softmax(osum/max(cnt,1) + x @ root2 + bias2) ----------------
__global__ void k_out(const float4* __restrict__ root2, const float4* __restrict__ bias2,
                      float4* __restrict__ out) {
    __shared__ float4 sr2[HH];
    __shared__ float4 sb2;
    if (threadIdx.x < HH) sr2[threadIdx.x] = root2[threadIdx.x];
    if (threadIdx.x == 0) sb2 = bias2[0];
    __syncthreads();

    int n = blockIdx.x * blockDim.x + threadIdx.x;
    if (n >= NN) return;

    float inv = 1.f / fmaxf(g_cnt[n], 1.f);
    float4 os = g_osum[n];
    float4 acc;
    acc.x = os.x * inv + sb2.x;
    acc.y = os.y * inv + sb2.y;
    acc.z = os.z * inv + sb2.z;
    acc.w = os.w * inv + sb2.w;

    const float4* xr = g_x + n * 4;
    #pragma unroll
    for (int j = 0; j < 4; j++) {
        float4 xv = xr[j];
        fma4(acc, xv.x, sr2[j * 4 + 0]);
        fma4(acc, xv.y, sr2[j * 4 + 1]);
        fma4(acc, xv.z, sr2[j * 4 + 2]);
        fma4(acc, xv.w, sr2[j * 4 + 3]);
    }

    float m = fmaxf(fmaxf(acc.x, acc.y), fmaxf(acc.z, acc.w));
    float se = expf(acc.x - m) + expf(acc.y - m) + expf(acc.z - m) + expf(acc.w - m);
    float l = m + logf(se);
    float4 o;
    o.x = acc.x - l; o.y = acc.y - l; o.z = acc.z - l; o.w = acc.w - l;
    out[n] = o;
}

// ---------------- launcher (9 graph nodes) ----------------
extern "C" void kernel_launch(void* const* d_in, const int* in_sizes, int n_in,
                              void* d_out, int out_size) {
    const int*    ei        = (const int*)d_in[0];         // edge_index [2,E] int32
    const int*    et        = (const int*)d_in[1];         // edge_type  [E]   int32
    // d_in[2] edge_norm: unused by the reference forward
    const float*  basis1    = (const float*)d_in[3];       // [B,N,H]
    const float*  comp1     = (const float*)d_in[4];       // [R,B]
    const float4* root1     = (const float4*)d_in[5];      // [N,H]
    const float4* bias1     = (const float4*)d_in[6];      // [H]
    const float*  basis2    = (const float*)d_in[7];       // [B,H,C]
    const float*  comp2     = (const float*)d_in[8];       // [R,B]
    const float4* root2     = (const float4*)d_in[9];      // [H,C]
    const float4* bias2     = (const float4*)d_in[10];     // [C]
    float4* out = (float4*)d_out;

    (void)in_sizes; (void)n_in; (void)out_size;

    dim3 gw1((NH4 + 127) / 128, 2);
    k_d0    <<<NBLKN, 256>>>();
    k_d1    <<<(EE + 255) / 256, 256>>>(ei);
    k_d2    <<<NBLKN, 256>>>();
    k_d3    <<<(EE + 255) / 256, 256>>>(ei, et);
    k_w1    <<<gw1, 128>>>((const float4*)basis1, comp1);
    k_edge1n<<<(NN * 32 + 255) / 256, 256>>>();
    k_x_w2  <<<NBLKN + 1, 256>>>(root1, bias1, comp2, basis2);
    k_edge2n<<<(NN * 32 + 255) / 256, 256>>>();
    k_out   <<<(NN + 255) / 256, 256>>>(root2, bias2, out);
}

// round 14
// speedup vs baseline: 1.2175x; 1.2175x over previous
#include <cuda_runtime.h>
#include <cuda_fp16.h>
#include <cstdint>

#define NN 50000
#define EE 1600000
#define RR 50
#define BB 30
#define HH 16
#define CC 4
#define NH  (NN * HH)
#define NH2 (NN * HH / 2)   // 400000 half2 columns
#define RPAD2 52            // padded r-stride (mult of 4) for LDS.128 coef loads
#define NBLKN 196           // ceil(NN/256)

// ---------------- scratch (device globals; no allocation) ----------------
__device__ uint4  g_w1h[(size_t)RR * NN * 2];      // [R,N,H] fp16: 32B/row, 80MB
__device__ float4 g_w2[RR * HH];                   // [R,H,C] fp32
__device__ uint4  g_xsumh[NN * 2];                 // layer1 accumulator, fp16
__device__ float4 g_x[NN * HH / 4];                // relu'd hidden (fp32, for k_out)
__device__ uint4  g_xh[NN * 2];                    // relu'd hidden (fp16, edge2 gather)
__device__ float  g_cnt[NN];                       // in-degree (float)
__device__ float4 g_osum[NN];                      // layer2 accumulator [N,C] fp32

// fp32 v4 reduction
__device__ __forceinline__ void red4(float4* p, float4 v) {
    asm volatile("red.global.add.v4.f32 [%0], {%1, %2, %3, %4};"
                 :: "l"(p), "f"(v.x), "f"(v.y), "f"(v.z), "f"(v.w) : "memory");
}
// fp16x2 v4 reduction
__device__ __forceinline__ void red4h(uint4* p, uint4 v) {
    asm volatile("red.global.add.noftz.v4.f16x2 [%0], {%1, %2, %3, %4};"
                 :: "l"(p), "r"(v.x), "r"(v.y), "r"(v.z), "r"(v.w) : "memory");
}
__device__ __forceinline__ void fma4(float4& a, float s, float4 w) {
    a.x += s * w.x; a.y += s * w.y; a.z += s * w.z; a.w += s * w.w;
}
__device__ __forceinline__ unsigned int h2bits(__half2 h) { return *(unsigned int*)&h; }
__device__ __forceinline__ __half2 bits2h(unsigned int u) { return *(__half2*)&u; }

// ---------------- K1: single-pass w1 + accumulator zeroing (launch 1) ----------------
// One thread per half2 column (400K threads). 50 half2 accumulators, b-outer
// loop with MLP=2 prefetch, LDS.128 coefficient vectors, HFMA2. Basis read ONCE.
__global__ void __launch_bounds__(128) k_w1(const float2* __restrict__ basis1,
                                            const float* __restrict__ comp1) {
    __shared__ __align__(16) unsigned int schv[BB * RPAD2];  // [b][r] half2(c,c)
    for (int i = threadIdx.x; i < BB * RPAD2; i += blockDim.x) {
        int b = i / RPAD2, r = i - b * RPAD2;
        float c = (r < RR) ? comp1[r * BB + b] : 0.f;
        schv[i] = h2bits(__floats2half2_rn(c, c));
    }

    int i2 = blockIdx.x * blockDim.x + threadIdx.x;

    // fold in accumulator zeroing (disjoint arrays; consumed by later launches)
    if (i2 < NN * 2 + NN + NN) {
        if (i2 < NN * 2) {
            g_xsumh[i2] = make_uint4(0u, 0u, 0u, 0u);
        } else if (i2 < NN * 2 + NN) {
            g_osum[i2 - NN * 2] = make_float4(0.f, 0.f, 0.f, 0.f);
        } else {
            g_cnt[i2 - NN * 3] = 0.f;
        }
    }
    __syncthreads();

    if (i2 >= NH2) return;

    __half2 a[RR];
    const __half2 hz = __floats2half2_rn(0.f, 0.f);
    #pragma unroll
    for (int r = 0; r < RR; r++) a[r] = hz;

    float2 v = basis1[i2];   // b = 0
    #pragma unroll 1
    for (int b = 0; b < BB; b++) {
        float2 vn = make_float2(0.f, 0.f);
        if (b + 1 < BB) vn = basis1[(size_t)(b + 1) * NH2 + i2];  // prefetch (MLP=2)

        __half2 hv = __floats2half2_rn(v.x, v.y);
        const unsigned int* cb = &schv[b * RPAD2];

        #pragma unroll
        for (int rg = 0; rg < 12; rg++) {                 // r = 0..47, 4 at a time
            uint4 c4 = *(const uint4*)(cb + rg * 4);
            int r = rg * 4;
            a[r+0] = __hfma2(bits2h(c4.x), hv, a[r+0]);
            a[r+1] = __hfma2(bits2h(c4.y), hv, a[r+1]);
            a[r+2] = __hfma2(bits2h(c4.z), hv, a[r+2]);
            a[r+3] = __hfma2(bits2h(c4.w), hv, a[r+3]);
        }
        a[48] = __hfma2(bits2h(cb[48]), hv, a[48]);
        a[49] = __hfma2(bits2h(cb[49]), hv, a[49]);
        v = vn;
    }

    unsigned int* outp = (unsigned int*)g_w1h;
    #pragma unroll
    for (int r = 0; r < RR; r++)
        outp[(size_t)r * NH2 + i2] = h2bits(a[r]);   // lane-consecutive 4B: coalesced
}

// ---------------- K2: layer-1 edge pass (launch 2) ----------------
__global__ void k_edge1(const int* __restrict__ ei, const int* __restrict__ et) {
    int e = blockIdx.x * blockDim.x + threadIdx.x;
    if (e >= EE) return;
    int s = ei[e];
    int d = ei[EE + e];
    int t = et[e];
    const uint4* row = g_w1h + ((size_t)t * NN + s) * 2;
    uint4 a = row[0], b = row[1];
    uint4* dst = g_xsumh + d * 2;
    red4h(dst + 0, a);
    red4h(dst + 1, b);
    atomicAdd(&g_cnt[d], 1.0f);
}

// ---------------- K3: x = relu(mean + root1 + bias1), plus w2 build (launch 3) ----------------
__global__ void k_x_w2(const float4* __restrict__ root1, const float4* __restrict__ bias1,
                       const float* __restrict__ comp2, const float* __restrict__ basis2) {
    if (blockIdx.x == NBLKN) {
        __shared__ float sc[RR * BB];
        __shared__ float sb[BB * HH * CC];
        for (int i = threadIdx.x; i < RR * BB; i += blockDim.x) sc[i] = comp2[i];
        for (int i = threadIdx.x; i < BB * HH * CC; i += blockDim.x) sb[i] = basis2[i];
        __syncthreads();
        float* w2f = (float*)g_w2;
        for (int i = threadIdx.x; i < RR * HH * CC; i += blockDim.x) {
            int r = i / (HH * CC);
            int hc = i % (HH * CC);
            float acc = 0.f;
            #pragma unroll
            for (int b = 0; b < BB; b++) acc += sc[r * BB + b] * sb[b * HH * CC + hc];
            w2f[i] = acc;
        }
        return;
    }

    int n = blockIdx.x * blockDim.x + threadIdx.x;
    if (n >= NN) return;
    float inv = 1.f / fmaxf(g_cnt[n], 1.f);
    uint4 a = g_xsumh[n * 2];
    uint4 b = g_xsumh[n * 2 + 1];
    unsigned int w[8] = {a.x, a.y, a.z, a.w, b.x, b.y, b.z, b.w};
    unsigned int hx[8];
    #pragma unroll
    for (int j = 0; j < 4; j++) {
        float2 lo = __half22float2(bits2h(w[j * 2]));
        float2 hi = __half22float2(bits2h(w[j * 2 + 1]));
        float4 rv = root1[n * 4 + j];
        float4 bv = bias1[j];
        float4 o;
        o.x = fmaxf(lo.x * inv + rv.x + bv.x, 0.f);
        o.y = fmaxf(lo.y * inv + rv.y + bv.y, 0.f);
        o.z = fmaxf(hi.x * inv + rv.z + bv.z, 0.f);
        o.w = fmaxf(hi.y * inv + rv.w + bv.w, 0.f);
        g_x[n * 4 + j] = o;
        hx[j * 2]     = h2bits(__floats2half2_rn(o.x, o.y));
        hx[j * 2 + 1] = h2bits(__floats2half2_rn(o.z, o.w));
    }
    g_xh[n * 2]     = make_uint4(hx[0], hx[1], hx[2], hx[3]);
    g_xh[n * 2 + 1] = make_uint4(hx[4], hx[5], hx[6], hx[7]);
}

// ---------------- K4: layer-2 edge pass (launch 4) ----------------
__global__ void k_edge2(const int* __restrict__ ei, const int* __restrict__ et) {
    __shared__ unsigned long long sw2h[HH * 64];  // 8 KB, [h*64 + t] half4
    for (int i = threadIdx.x; i < RR * HH; i += blockDim.x) {
        int r = i / HH, h = i % HH;
        float4 w = g_w2[r * HH + h];
        uint2 p;
        p.x = h2bits(__floats2half2_rn(w.x, w.y));
        p.y = h2bits(__floats2half2_rn(w.z, w.w));
        sw2h[h * 64 + r] = *(unsigned long long*)&p;
    }
    __syncthreads();

    int e = blockIdx.x * blockDim.x + threadIdx.x;
    if (e >= EE) return;
    int s = ei[e];
    int d = ei[EE + e];
    int t = et[e];

    uint4 xa = g_xh[s * 2];
    uint4 xb = g_xh[s * 2 + 1];
    unsigned int xw[8] = {xa.x, xa.y, xa.z, xa.w, xb.x, xb.y, xb.z, xb.w};
    float xf[16];
    #pragma unroll
    for (int j = 0; j < 8; j++) {
        float2 f = __half22float2(bits2h(xw[j]));
        xf[j * 2] = f.x;
        xf[j * 2 + 1] = f.y;
    }

    float4 acc = make_float4(0.f, 0.f, 0.f, 0.f);
    #pragma unroll
    for (int h = 0; h < HH; h++) {
        unsigned long long wp = sw2h[h * 64 + t];
        uint2 p = *(uint2*)&wp;
        float2 wlo = __half22float2(bits2h(p.x));
        float2 whi = __half22float2(bits2h(p.y));
        fma4(acc, xf[h], make_float4(wlo.x, wlo.y, whi.x, whi.y));
    }

    red4(&g_osum[d], acc);
}

// ---------------- K5: out = log_softmax(osum/max(cnt,1) + x @ root2 + bias2) ----------------
__global__ void k_out(const float4* __restrict__ root2, const float4* __restrict__ bias2,
                      float4* __restrict__ out) {
    __shared__ float4 sr2[HH];
    __shared__ float4 sb2;
    if (threadIdx.x < HH) sr2[threadIdx.x] = root2[threadIdx.x];
    if (threadIdx.x == 0) sb2 = bias2[0];
    __syncthreads();

    int n = blockIdx.x * blockDim.x + threadIdx.x;
    if (n >= NN) return;

    float inv = 1.f / fmaxf(g_cnt[n], 1.f);
    float4 os = g_osum[n];
    float4 acc;
    acc.x = os.x * inv + sb2.x;
    acc.y = os.y * inv + sb2.y;
    acc.z = os.z * inv + sb2.z;
    acc.w = os.w * inv + sb2.w;

    const float4* xr = g_x + n * 4;
    #pragma unroll
    for (int j = 0; j < 4; j++) {
        float4 xv = xr[j];
        fma4(acc, xv.x, sr2[j * 4 + 0]);
        fma4(acc, xv.y, sr2[j * 4 + 1]);
        fma4(acc, xv.z, sr2[j * 4 + 2]);
        fma4(acc, xv.w, sr2[j * 4 + 3]);
    }

    float m = fmaxf(fmaxf(acc.x, acc.y), fmaxf(acc.z, acc.w));
    float se = expf(acc.x - m) + expf(acc.y - m) + expf(acc.z - m) + expf(acc.w - m);
    float l = m + logf(se);
    float4 o;
    o.x = acc.x - l; o.y = acc.y - l; o.z = acc.z - l; o.w = acc.w - l;
    out[n] = o;
}

// ---------------- launcher (5 graph nodes) ----------------
extern "C" void kernel_launch(void* const* d_in, const int* in_sizes, int n_in,
                              void* d_out, int out_size) {
    const int*    ei        = (const int*)d_in[0];         // edge_index [2,E] int32
    const int*    et        = (const int*)d_in[1];         // edge_type  [E]   int32
    // d_in[2] edge_norm: unused by the reference forward
    const float*  basis1    = (const float*)d_in[3];       // [B,N,H]
    const float*  comp1     = (const float*)d_in[4];       // [R,B]
    const float4* root1     = (const float4*)d_in[5];      // [N,H]
    const float4* bias1     = (const float4*)d_in[6];      // [H]
    const float*  basis2    = (const float*)d_in[7];       // [B,H,C]
    const float*  comp2     = (const float*)d_in[8];       // [R,B]
    const float4* root2     = (const float4*)d_in[9];      // [H,C]
    const float4* bias2     = (const float4*)d_in[10];     // [C]
    float4* out = (float4*)d_out;

    (void)in_sizes; (void)n_in; (void)out_size;

    k_w1   <<<(NH2 + 127) / 128, 128>>>((const float2*)basis1, comp1);
    k_edge1<<<(EE + 255) / 256, 256>>>(ei, et);
    k_x_w2 <<<NBLKN + 1, 256>>>(root1, bias1, comp2, basis2);
    k_edge2<<<(EE + 255) / 256, 256>>>(ei, et);
    k_out  <<<(NN + 255) / 256, 256>>>(root2, bias2, out);
}

// round 15
// speedup vs baseline: 1.2753x; 1.0475x over previous
#include <cuda_runtime.h>
#include <cuda_fp16.h>
#include <cstdint>

#define NN 50000
#define EE 1600000
#define RR 50
#define BB 30
#define HH 16
#define CC 4
#define NH  (NN * HH)
#define NH2 (NN * HH / 2)   // 400000 half2 columns (divisible by 128)
#define RCH 25              // relations per chunk
#define RPADC 28            // padded chunk stride for LDS.128 coef loads
#define NBLKN 196           // ceil(NN/256)

// ---------------- scratch (device globals; no allocation) ----------------
__device__ uint4  g_w1h[(size_t)RR * NN * 2];      // [R,N,H] fp16: 32B/row, 80MB
__device__ uint4  g_w2h[RR * 8];                   // [R][H][C] fp16: 128B/row
__device__ uint4  g_xsumh[NN * 2];                 // layer1 accumulator, fp16
__device__ float4 g_x[NN * HH / 4];                // relu'd hidden (fp32, for k_out)
__device__ uint4  g_xh[NN * 2];                    // relu'd hidden (fp16, edge2 gather)
__device__ float  g_cnt[NN];                       // in-degree (float)
__device__ float4 g_osum[NN];                      // layer2 accumulator [N,C] fp32

// fp32 v4 reduction
__device__ __forceinline__ void red4(float4* p, float4 v) {
    asm volatile("red.global.add.v4.f32 [%0], {%1, %2, %3, %4};"
                 :: "l"(p), "f"(v.x), "f"(v.y), "f"(v.z), "f"(v.w) : "memory");
}
// fp16x2 v4 reduction
__device__ __forceinline__ void red4h(uint4* p, uint4 v) {
    asm volatile("red.global.add.noftz.v4.f16x2 [%0], {%1, %2, %3, %4};"
                 :: "l"(p), "r"(v.x), "r"(v.y), "r"(v.z), "r"(v.w) : "memory");
}
__device__ __forceinline__ void fma4(float4& a, float s, float4 w) {
    a.x += s * w.x; a.y += s * w.y; a.z += s * w.z; a.w += s * w.w;
}
__device__ __forceinline__ unsigned int h2bits(__half2 h) { return *(unsigned int*)&h; }
__device__ __forceinline__ __half2 bits2h(unsigned int u) { return *(__half2*)&u; }

// ---------------- K1: w1 (smem basis tile, 2 chunks of 25 accumulators) ----------------
// Block owns 128 half2 columns. Phase 0: stream basis tile into smem (15 KB,
// conflict-free [b][tid]). Phase 1: two relation chunks of 25; 25 HFMA2 accs,
// uniform-broadcast LDS.128 coef vectors. Basis read from DRAM once.
__global__ void __launch_bounds__(128, 6) k_w1(const float2* __restrict__ basis1,
                                               const float* __restrict__ comp1) {
    __shared__ __align__(16) unsigned int schv[2][BB * RPADC]; // coefs half2(c,c) [chunk][b][r]
    __shared__ unsigned int sbas[BB * 128];                    // basis tile half2 [b][tid]

    int tid = threadIdx.x;
    int i2 = blockIdx.x * 128 + tid;

    for (int i = tid; i < 2 * BB * RPADC; i += 128) {
        int ch = i / (BB * RPADC);
        int j  = i - ch * (BB * RPADC);
        int b = j / RPADC, r = j - b * RPADC;
        float c = (r < RCH) ? comp1[(ch * RCH + r) * BB + b] : 0.f;
        schv[ch][j] = h2bits(__floats2half2_rn(c, c));
    }

    // fold in accumulator zeroing (disjoint arrays; consumed by later launches)
    if (i2 < NN * 2 + NN + NN) {
        if (i2 < NN * 2) {
            g_xsumh[i2] = make_uint4(0u, 0u, 0u, 0u);
        } else if (i2 < NN * 2 + NN) {
            g_osum[i2 - NN * 2] = make_float4(0.f, 0.f, 0.f, 0.f);
        } else {
            g_cnt[i2 - NN * 3] = 0.f;
        }
    }

    // phase 0: stream basis columns into smem (coalesced LDG.64 per b)
    #pragma unroll 6
    for (int b = 0; b < BB; b++) {
        float2 v = basis1[(size_t)b * NH2 + i2];
        sbas[b * 128 + tid] = h2bits(__floats2half2_rn(v.x, v.y));
    }
    __syncthreads();

    unsigned int* outp = (unsigned int*)g_w1h;

    #pragma unroll
    for (int ch = 0; ch < 2; ch++) {
        __half2 a[RCH];
        const __half2 hz = __floats2half2_rn(0.f, 0.f);
        #pragma unroll
        for (int r = 0; r < RCH; r++) a[r] = hz;

        #pragma unroll 1
        for (int b = 0; b < BB; b++) {
            __half2 hv = bits2h(sbas[b * 128 + tid]);   // LDS.32, conflict-free
            const unsigned int* cb = &schv[ch][b * RPADC];
            #pragma unroll
            for (int rg = 0; rg < 6; rg++) {            // r = 0..23
                uint4 c4 = *(const uint4*)(cb + rg * 4);  // uniform: broadcast
                int r = rg * 4;
                a[r+0] = __hfma2(bits2h(c4.x), hv, a[r+0]);
                a[r+1] = __hfma2(bits2h(c4.y), hv, a[r+1]);
                a[r+2] = __hfma2(bits2h(c4.z), hv, a[r+2]);
                a[r+3] = __hfma2(bits2h(c4.w), hv, a[r+3]);
            }
            a[24] = __hfma2(bits2h(cb[24]), hv, a[24]);
        }

        #pragma unroll
        for (int r = 0; r < RCH; r++)
            outp[(size_t)(ch * RCH + r) * NH2 + i2] = h2bits(a[r]);  // coalesced
    }
}

// ---------------- K2: layer-1 edge pass (LTS-atomic floor) ----------------
__global__ void k_edge1(const int* __restrict__ ei, const int* __restrict__ et) {
    int e = blockIdx.x * blockDim.x + threadIdx.x;
    if (e >= EE) return;
    int s = ei[e];
    int d = ei[EE + e];
    int t = et[e];
    const uint4* row = g_w1h + ((size_t)t * NN + s) * 2;
    uint4 a = row[0], b = row[1];
    uint4* dst = g_xsumh + d * 2;
    red4h(dst + 0, a);
    red4h(dst + 1, b);
    atomicAdd(&g_cnt[d], 1.0f);
}

// ---------------- K3: x = relu(mean + root1 + bias1), plus fp16 w2 build ----------------
__global__ void k_x_w2(const float4* __restrict__ root1, const float4* __restrict__ bias1,
                       const float* __restrict__ comp2, const float* __restrict__ basis2) {
    if (blockIdx.x == NBLKN) {
        __shared__ float sc[RR * BB];
        __shared__ float sb[BB * HH * CC];
        for (int i = threadIdx.x; i < RR * BB; i += blockDim.x) sc[i] = comp2[i];
        for (int i = threadIdx.x; i < BB * HH * CC; i += blockDim.x) sb[i] = basis2[i];
        __syncthreads();
        __half* w2p = (__half*)g_w2h;
        for (int i = threadIdx.x; i < RR * HH * CC; i += blockDim.x) {
            int r = i / (HH * CC);
            int hc = i % (HH * CC);
            float acc = 0.f;
            #pragma unroll
            for (int b = 0; b < BB; b++) acc += sc[r * BB + b] * sb[b * HH * CC + hc];
            w2p[r * 64 + hc] = __float2half(acc);   // [t][h][c] halves, 128B rows
        }
        return;
    }

    int n = blockIdx.x * blockDim.x + threadIdx.x;
    if (n >= NN) return;
    float inv = 1.f / fmaxf(g_cnt[n], 1.f);
    uint4 a = g_xsumh[n * 2];
    uint4 b = g_xsumh[n * 2 + 1];
    unsigned int w[8] = {a.x, a.y, a.z, a.w, b.x, b.y, b.z, b.w};
    unsigned int hx[8];
    #pragma unroll
    for (int j = 0; j < 4; j++) {
        float2 lo = __half22float2(bits2h(w[j * 2]));
        float2 hi = __half22float2(bits2h(w[j * 2 + 1]));
        float4 rv = root1[n * 4 + j];
        float4 bv = bias1[j];
        float4 o;
        o.x = fmaxf(lo.x * inv + rv.x + bv.x, 0.f);
        o.y = fmaxf(lo.y * inv + rv.y + bv.y, 0.f);
        o.z = fmaxf(hi.x * inv + rv.z + bv.z, 0.f);
        o.w = fmaxf(hi.y * inv + rv.w + bv.w, 0.f);
        g_x[n * 4 + j] = o;
        hx[j * 2]     = h2bits(__floats2half2_rn(o.x, o.y));
        hx[j * 2 + 1] = h2bits(__floats2half2_rn(o.z, o.w));
    }
    g_xh[n * 2]     = make_uint4(hx[0], hx[1], hx[2], hx[3]);
    g_xh[n * 2 + 1] = make_uint4(hx[4], hx[5], hx[6], hx[7]);
}

// ---------------- K4: layer-2, 4 lanes per edge ----------------
// lane sub handles h = sub*4..sub*4+3: 8B of x, 32B of the fp16 w2 row
// (128B = one cache line per edge). Quad shfl-reduce; leader REDs v4.f32.
__global__ void k_edge2(const int* __restrict__ ei, const int* __restrict__ et) {
    int gt = blockIdx.x * blockDim.x + threadIdx.x;
    int e   = gt >> 2;
    int sub = gt & 3;
    if (e >= EE) return;
    int s = ei[e];
    int d = ei[EE + e];
    int t = et[e];

    // x quarter: 4 halves (h = sub*4 .. sub*4+3)
    uint2 xq = *((const uint2*)g_xh + (size_t)s * 4 + sub);
    float2 x01 = __half22float2(bits2h(xq.x));
    float2 x23 = __half22float2(bits2h(xq.y));

    // w quarter: rows h=sub*4..+3, 4 c each = 32B
    const uint4* wrow = g_w2h + t * 8 + sub * 2;
    uint4 w0 = wrow[0];   // h0: (c0,c1),(c2,c3); h1: (c0,c1),(c2,c3)
    uint4 w1 = wrow[1];   // h2, h3

    float4 acc = make_float4(0.f, 0.f, 0.f, 0.f);
    {
        float2 a = __half22float2(bits2h(w0.x)), b = __half22float2(bits2h(w0.y));
        fma4(acc, x01.x, make_float4(a.x, a.y, b.x, b.y));
        a = __half22float2(bits2h(w0.z)); b = __half22float2(bits2h(w0.w));
        fma4(acc, x01.y, make_float4(a.x, a.y, b.x, b.y));
        a = __half22float2(bits2h(w1.x)); b = __half22float2(bits2h(w1.y));
        fma4(acc, x23.x, make_float4(a.x, a.y, b.x, b.y));
        a = __half22float2(bits2h(w1.z)); b = __half22float2(bits2h(w1.w));
        fma4(acc, x23.y, make_float4(a.x, a.y, b.x, b.y));
    }

    // reduce over the 4 lanes of this edge
    #pragma unroll
    for (int o = 1; o < 4; o <<= 1) {
        acc.x += __shfl_xor_sync(0xffffffffu, acc.x, o);
        acc.y += __shfl_xor_sync(0xffffffffu, acc.y, o);
        acc.z += __shfl_xor_sync(0xffffffffu, acc.z, o);
        acc.w += __shfl_xor_sync(0xffffffffu, acc.w, o);
    }

    if (sub == 0) red4(&g_osum[d], acc);
}

// ---------------- K5: out = log_softmax(osum/max(cnt,1) + x @ root2 + bias2) ----------------
__global__ void k_out(const float4* __restrict__ root2, const float4* __restrict__ bias2,
                      float4* __restrict__ out) {
    __shared__ float4 sr2[HH];
    __shared__ float4 sb2;
    if (threadIdx.x < HH) sr2[threadIdx.x] = root2[threadIdx.x];
    if (threadIdx.x == 0) sb2 = bias2[0];
    __syncthreads();

    int n = blockIdx.x * blockDim.x + threadIdx.x;
    if (n >= NN) return;

    float inv = 1.f / fmaxf(g_cnt[n], 1.f);
    float4 os = g_osum[n];
    float4 acc;
    acc.x = os.x * inv + sb2.x;
    acc.y = os.y * inv + sb2.y;
    acc.z = os.z * inv + sb2.z;
    acc.w = os.w * inv + sb2.w;

    const float4* xr = g_x + n * 4;
    #pragma unroll
    for (int j = 0; j < 4; j++) {
        float4 xv = xr[j];
        fma4(acc, xv.x, sr2[j * 4 + 0]);
        fma4(acc, xv.y, sr2[j * 4 + 1]);
        fma4(acc, xv.z, sr2[j * 4 + 2]);
        fma4(acc, xv.w, sr2[j * 4 + 3]);
    }

    float m = fmaxf(fmaxf(acc.x, acc.y), fmaxf(acc.z, acc.w));
    float se = expf(acc.x - m) + expf(acc.y - m) + expf(acc.z - m) + expf(acc.w - m);
    float l = m + logf(se);
    float4 o;
    o.x = acc.x - l; o.y = acc.y - l; o.z = acc.z - l; o.w = acc.w - l;
    out[n] = o;
}

// ---------------- launcher (5 graph nodes) ----------------
extern "C" void kernel_launch(void* const* d_in, const int* in_sizes, int n_in,
                              void* d_out, int out_size) {
    const int*    ei        = (const int*)d_in[0];         // edge_index [2,E] int32
    const int*    et        = (const int*)d_in[1];         // edge_type  [E]   int32
    // d_in[2] edge_norm: unused by the reference forward
    const float*  basis1    = (const float*)d_in[3];       // [B,N,H]
    const float*  comp1     = (const float*)d_in[4];       // [R,B]
    const float4* root1     = (const float4*)d_in[5];      // [N,H]
    const float4* bias1     = (const float4*)d_in[6];      // [H]
    const float*  basis2    = (const float*)d_in[7];       // [B,H,C]
    const float*  comp2     = (const float*)d_in[8];       // [R,B]
    const float4* root2     = (const float4*)d_in[9];      // [H,C]
    const float4* bias2     = (const float4*)d_in[10];     // [C]
    float4* out = (float4*)d_out;

    (void)in_sizes; (void)n_in; (void)out_size;

    k_w1   <<<NH2 / 128, 128>>>((const float2*)basis1, comp1);
    k_edge1<<<(EE + 255) / 256, 256>>>(ei, et);
    k_x_w2 <<<NBLKN + 1, 256>>>(root1, bias1, comp2, basis2);
    k_edge2<<<(EE * 4 + 255) / 256, 256>>>(ei, et);
    k_out  <<<(NN + 255) / 256, 256>>>(root2, bias2, out);
}

// round 16
// speedup vs baseline: 1.3503x; 1.0588x over previous
#include <cuda_runtime.h>
#include <cuda_fp16.h>
#include <cstdint>

#define NN 50000
#define EE 1600000
#define RR 50
#define BB 30
#define HH 16
#define CC 4
#define NH  (NN * HH)
#define NH2 (NN * HH / 2)   // 400000 half2 columns (divisible by 128)
#define RCH 25              // relations per chunk
#define RPADC 28            // padded chunk stride for LDS.128 coef loads
#define NBLKN 196           // ceil(NN/256)

// ---------------- scratch (device globals; no allocation) ----------------
__device__ uint4  g_w1h[(size_t)RR * NN * 2];      // [R,N,H] fp16: 32B/row, 80MB
__device__ uint4  g_w2t[RR * 8];                   // [t][c][h] fp16: 32B per (t,c) row
__device__ uint4  g_xsumh[NN * 2];                 // layer1 accumulator, fp16
__device__ float4 g_x[NN * HH / 4];                // relu'd hidden (fp32, for k_out)
__device__ uint4  g_xh[NN * 2];                    // relu'd hidden (fp16, edge2 gather)
__device__ float  g_cnt[NN];                       // in-degree (float)
__device__ float4 g_osum[NN];                      // layer2 accumulator [N,C] fp32

// fp32 scalar reduction
__device__ __forceinline__ void red1(float* p, float v) {
    asm volatile("red.global.add.f32 [%0], %1;" :: "l"(p), "f"(v) : "memory");
}
// fp16x2 v4 reduction
__device__ __forceinline__ void red4h(uint4* p, uint4 v) {
    asm volatile("red.global.add.noftz.v4.f16x2 [%0], {%1, %2, %3, %4};"
                 :: "l"(p), "r"(v.x), "r"(v.y), "r"(v.z), "r"(v.w) : "memory");
}
__device__ __forceinline__ void fma4(float4& a, float s, float4 w) {
    a.x += s * w.x; a.y += s * w.y; a.z += s * w.z; a.w += s * w.w;
}
__device__ __forceinline__ unsigned int h2bits(__half2 h) { return *(unsigned int*)&h; }
__device__ __forceinline__ __half2 bits2h(unsigned int u) { return *(__half2*)&u; }

// ---------------- K1: w1 (smem basis tile, 2 chunks of 25 accumulators) ----------------
__global__ void __launch_bounds__(128, 6) k_w1(const float2* __restrict__ basis1,
                                               const float* __restrict__ comp1) {
    __shared__ __align__(16) unsigned int schv[2][BB * RPADC]; // coefs half2(c,c)
    __shared__ unsigned int sbas[BB * 128];                    // basis tile half2 [b][tid]

    int tid = threadIdx.x;
    int i2 = blockIdx.x * 128 + tid;

    for (int i = tid; i < 2 * BB * RPADC; i += 128) {
        int ch = i / (BB * RPADC);
        int j  = i - ch * (BB * RPADC);
        int b = j / RPADC, r = j - b * RPADC;
        float c = (r < RCH) ? comp1[(ch * RCH + r) * BB + b] : 0.f;
        schv[ch][j] = h2bits(__floats2half2_rn(c, c));
    }

    // fold in accumulator zeroing
    if (i2 < NN * 2 + NN + NN) {
        if (i2 < NN * 2) {
            g_xsumh[i2] = make_uint4(0u, 0u, 0u, 0u);
        } else if (i2 < NN * 2 + NN) {
            g_osum[i2 - NN * 2] = make_float4(0.f, 0.f, 0.f, 0.f);
        } else {
            g_cnt[i2 - NN * 3] = 0.f;
        }
    }

    #pragma unroll 6
    for (int b = 0; b < BB; b++) {
        float2 v = basis1[(size_t)b * NH2 + i2];
        sbas[b * 128 + tid] = h2bits(__floats2half2_rn(v.x, v.y));
    }
    __syncthreads();

    unsigned int* outp = (unsigned int*)g_w1h;

    #pragma unroll
    for (int ch = 0; ch < 2; ch++) {
        __half2 a[RCH];
        const __half2 hz = __floats2half2_rn(0.f, 0.f);
        #pragma unroll
        for (int r = 0; r < RCH; r++) a[r] = hz;

        #pragma unroll 1
        for (int b = 0; b < BB; b++) {
            __half2 hv = bits2h(sbas[b * 128 + tid]);
            const unsigned int* cb = &schv[ch][b * RPADC];
            #pragma unroll
            for (int rg = 0; rg < 6; rg++) {
                uint4 c4 = *(const uint4*)(cb + rg * 4);
                int r = rg * 4;
                a[r+0] = __hfma2(bits2h(c4.x), hv, a[r+0]);
                a[r+1] = __hfma2(bits2h(c4.y), hv, a[r+1]);
                a[r+2] = __hfma2(bits2h(c4.z), hv, a[r+2]);
                a[r+3] = __hfma2(bits2h(c4.w), hv, a[r+3]);
            }
            a[24] = __hfma2(bits2h(cb[24]), hv, a[24]);
        }

        #pragma unroll
        for (int r = 0; r < RCH; r++)
            outp[(size_t)(ch * RCH + r) * NH2 + i2] = h2bits(a[r]);
    }
}

// ---------------- K2: layer-1 edge pass (LTS-atomic floor) ----------------
__global__ void k_edge1(const int* __restrict__ ei, const int* __restrict__ et) {
    int e = blockIdx.x * blockDim.x + threadIdx.x;
    if (e >= EE) return;
    int s = ei[e];
    int d = ei[EE + e];
    int t = et[e];
    const uint4* row = g_w1h + ((size_t)t * NN + s) * 2;
    uint4 a = row[0], b = row[1];
    uint4* dst = g_xsumh + d * 2;
    red4h(dst + 0, a);
    red4h(dst + 1, b);
    asm volatile("red.global.add.f32 [%0], %1;" :: "l"(&g_cnt[d]), "f"(1.0f) : "memory");
}

// ---------------- K3: x = relu(mean + root1 + bias1), plus transposed fp16 w2 build ----------------
__global__ void k_x_w2(const float4* __restrict__ root1, const float4* __restrict__ bias1,
                       const float* __restrict__ comp2, const float* __restrict__ basis2) {
    if (blockIdx.x == NBLKN) {
        __shared__ float sc[RR * BB];
        __shared__ float sb[BB * HH * CC];
        for (int i = threadIdx.x; i < RR * BB; i += blockDim.x) sc[i] = comp2[i];
        for (int i = threadIdx.x; i < BB * HH * CC; i += blockDim.x) sb[i] = basis2[i];
        __syncthreads();
        __half* w2p = (__half*)g_w2t;
        for (int i = threadIdx.x; i < RR * HH * CC; i += blockDim.x) {
            int r = i / (HH * CC);
            int hc = i % (HH * CC);
            int h = hc / CC, c = hc % CC;
            float acc = 0.f;
            #pragma unroll
            for (int b = 0; b < BB; b++) acc += sc[r * BB + b] * sb[b * HH * CC + hc];
            w2p[r * 64 + c * 16 + h] = __float2half(acc);   // transposed [t][c][h]
        }
        return;
    }

    int n = blockIdx.x * blockDim.x + threadIdx.x;
    if (n >= NN) return;
    float inv = 1.f / fmaxf(g_cnt[n], 1.f);
    uint4 a = g_xsumh[n * 2];
    uint4 b = g_xsumh[n * 2 + 1];
    unsigned int w[8] = {a.x, a.y, a.z, a.w, b.x, b.y, b.z, b.w};
    unsigned int hx[8];
    #pragma unroll
    for (int j = 0; j < 4; j++) {
        float2 lo = __half22float2(bits2h(w[j * 2]));
        float2 hi = __half22float2(bits2h(w[j * 2 + 1]));
        float4 rv = root1[n * 4 + j];
        float4 bv = bias1[j];
        float4 o;
        o.x = fmaxf(lo.x * inv + rv.x + bv.x, 0.f);
        o.y = fmaxf(lo.y * inv + rv.y + bv.y, 0.f);
        o.z = fmaxf(hi.x * inv + rv.z + bv.z, 0.f);
        o.w = fmaxf(hi.y * inv + rv.w + bv.w, 0.f);
        g_x[n * 4 + j] = o;
        hx[j * 2]     = h2bits(__floats2half2_rn(o.x, o.y));
        hx[j * 2 + 1] = h2bits(__floats2half2_rn(o.z, o.w));
    }
    g_xh[n * 2]     = make_uint4(hx[0], hx[1], hx[2], hx[3]);
    g_xh[n * 2 + 1] = make_uint4(hx[4], hx[5], hx[6], hx[7]);
}

// ---------------- K4: layer-2, 4 lanes per edge, NO shuffles ----------------
// lane sub = output class c. Loads full x row (broadcast within quad) and its
// 32B w2t[t][c][:] row; fp32 scalar accumulation; scalar RED to osum[d].c.
__global__ void k_edge2(const int* __restrict__ ei, const int* __restrict__ et) {
    int gt = blockIdx.x * blockDim.x + threadIdx.x;
    int e   = gt >> 2;
    int sub = gt & 3;
    if (e >= EE) return;
    int s = ei[e];
    int d = ei[EE + e];
    int t = et[e];

    const uint4* xr = g_xh + (size_t)s * 2;
    uint4 xa = xr[0], xb = xr[1];                 // 16 halves of x (broadcast in quad)
    const uint4* wr = g_w2t + t * 8 + sub * 2;
    uint4 w0 = wr[0], w1 = wr[1];                 // 16 halves of w2t[t][sub][:]

    float acc = 0.f;
    {
        float2 xf, wf;
        xf = __half22float2(bits2h(xa.x)); wf = __half22float2(bits2h(w0.x));
        acc = fmaf(xf.x, wf.x, fmaf(xf.y, wf.y, acc));
        xf = __half22float2(bits2h(xa.y)); wf = __half22float2(bits2h(w0.y));
        acc = fmaf(xf.x, wf.x, fmaf(xf.y, wf.y, acc));
        xf = __half22float2(bits2h(xa.z)); wf = __half22float2(bits2h(w0.z));
        acc = fmaf(xf.x, wf.x, fmaf(xf.y, wf.y, acc));
        xf = __half22float2(bits2h(xa.w)); wf = __half22float2(bits2h(w0.w));
        acc = fmaf(xf.x, wf.x, fmaf(xf.y, wf.y, acc));
        xf = __half22float2(bits2h(xb.x)); wf = __half22float2(bits2h(w1.x));
        acc = fmaf(xf.x, wf.x, fmaf(xf.y, wf.y, acc));
        xf = __half22float2(bits2h(xb.y)); wf = __half22float2(bits2h(w1.y));
        acc = fmaf(xf.x, wf.x, fmaf(xf.y, wf.y, acc));
        xf = __half22float2(bits2h(xb.z)); wf = __half22float2(bits2h(w1.z));
        acc = fmaf(xf.x, wf.x, fmaf(xf.y, wf.y, acc));
        xf = __half22float2(bits2h(xb.w)); wf = __half22float2(bits2h(w1.w));
        acc = fmaf(xf.x, wf.x, fmaf(xf.y, wf.y, acc));
    }

    red1((float*)g_osum + (size_t)d * 4 + sub, acc);
}

// ---------------- K5: out = log_softmax(osum/max(cnt,1) + x @ root2 + bias2) ----------------
__global__ void k_out(const float4* __restrict__ root2, const float4* __restrict__ bias2,
                      float4* __restrict__ out) {
    __shared__ float4 sr2[HH];
    __shared__ float4 sb2;
    if (threadIdx.x < HH) sr2[threadIdx.x] = root2[threadIdx.x];
    if (threadIdx.x == 0) sb2 = bias2[0];
    __syncthreads();

    int n = blockIdx.x * blockDim.x + threadIdx.x;
    if (n >= NN) return;

    float inv = 1.f / fmaxf(g_cnt[n], 1.f);
    float4 os = g_osum[n];
    float4 acc;
    acc.x = os.x * inv + sb2.x;
    acc.y = os.y * inv + sb2.y;
    acc.z = os.z * inv + sb2.z;
    acc.w = os.w * inv + sb2.w;

    const float4* xr = g_x + n * 4;
    #pragma unroll
    for (int j = 0; j < 4; j++) {
        float4 xv = xr[j];
        fma4(acc, xv.x, sr2[j * 4 + 0]);
        fma4(acc, xv.y, sr2[j * 4 + 1]);
        fma4(acc, xv.z, sr2[j * 4 + 2]);
        fma4(acc, xv.w, sr2[j * 4 + 3]);
    }

    float m = fmaxf(fmaxf(acc.x, acc.y), fmaxf(acc.z, acc.w));
    float se = expf(acc.x - m) + expf(acc.y - m) + expf(acc.z - m) + expf(acc.w - m);
    float l = m + logf(se);
    float4 o;
    o.x = acc.x - l; o.y = acc.y - l; o.z = acc.z - l; o.w = acc.w - l;
    out[n] = o;
}

// ---------------- launcher (5 graph nodes) ----------------
extern "C" void kernel_launch(void* const* d_in, const int* in_sizes, int n_in,
                              void* d_out, int out_size) {
    const int*    ei        = (const int*)d_in[0];         // edge_index [2,E] int32
    const int*    et        = (const int*)d_in[1];         // edge_type  [E]   int32
    // d_in[2] edge_norm: unused by the reference forward
    const float*  basis1    = (const float*)d_in[3];       // [B,N,H]
    const float*  comp1     = (const float*)d_in[4];       // [R,B]
    const float4* root1     = (const float4*)d_in[5];      // [N,H]
    const float4* bias1     = (const float4*)d_in[6];      // [H]
    const float*  basis2    = (const float*)d_in[7];       // [B,H,C]
    const float*  comp2     = (const float*)d_in[8];       // [R,B]
    const float4* root2     = (const float4*)d_in[9];      // [H,C]
    const float4* bias2     = (const float4*)d_in[10];     // [C]
    float4* out = (float4*)d_out;

    (void)in_sizes; (void)n_in; (void)out_size;

    k_w1   <<<NH2 / 128, 128>>>((const float2*)basis1, comp1);
    k_edge1<<<(EE + 255) / 256, 256>>>(ei, et);
    k_x_w2 <<<NBLKN + 1, 256>>>(root1, bias1, comp2, basis2);
    k_edge2<<<(EE * 4 + 255) / 256, 256>>>(ei, et);
    k_out  <<<(NN + 255) / 256, 256>>>(root2, bias2, out);
}

// round 17
// speedup vs baseline: 1.3881x; 1.0280x over previous
#include <cuda_runtime.h>
#include <cuda_fp16.h>
#include <cstdint>

#define NN 50000
#define EE 1600000
#define RR 50
#define BB 30
#define HH 16
#define CC 4
#define NH  (NN * HH)       // 800000 GEMM columns
#define NBLKN 196           // ceil(NN/256)

// ---------------- scratch (device globals; no allocation) ----------------
__device__ uint4  g_w1h[(size_t)RR * NN * 2];      // [R,N,H] fp16: 32B/row, 80MB
__device__ uint4  g_w2t[RR * 8];                   // [t][c][h] fp16: 32B per (t,c) row
__device__ uint4  g_xsumh[NN * 2];                 // layer1 accumulator, fp16
__device__ float4 g_x[NN * HH / 4];                // relu'd hidden (fp32, for k_out)
__device__ uint4  g_xh[NN * 2];                    // relu'd hidden (fp16, edge2 gather)
__device__ float  g_cnt[NN];                       // in-degree (float)
__device__ float4 g_osum[NN];                      // layer2 accumulator [N,C] fp32

// fp32 scalar reduction
__device__ __forceinline__ void red1(float* p, float v) {
    asm volatile("red.global.add.f32 [%0], %1;" :: "l"(p), "f"(v) : "memory");
}
// fp16x2 v4 reduction
__device__ __forceinline__ void red4h(uint4* p, uint4 v) {
    asm volatile("red.global.add.noftz.v4.f16x2 [%0], {%1, %2, %3, %4};"
                 :: "l"(p), "r"(v.x), "r"(v.y), "r"(v.z), "r"(v.w) : "memory");
}
__device__ __forceinline__ void fma4(float4& a, float s, float4 w) {
    a.x += s * w.x; a.y += s * w.y; a.z += s * w.z; a.w += s * w.w;
}
__device__ __forceinline__ unsigned int h2bits(__half2 h) { return *(unsigned int*)&h; }
__device__ __forceinline__ __half2 bits2h(unsigned int u) { return *(__half2*)&u; }

// m16n8k16 row.col f32.f16.f16.f32 (HMMA fallback path; baseline PTX, sm_80+)
__device__ __forceinline__ void mma16816(float& d0, float& d1, float& d2, float& d3,
                                         unsigned int a0, unsigned int a1,
                                         unsigned int a2, unsigned int a3,
                                         unsigned int b0, unsigned int b1) {
    asm volatile(
        "mma.sync.aligned.m16n8k16.row.col.f32.f16.f16.f32 "
        "{%0,%1,%2,%3}, {%4,%5,%6,%7}, {%8,%9}, {%0,%1,%2,%3};"
        : "+f"(d0), "+f"(d1), "+f"(d2), "+f"(d3)
        : "r"(a0), "r"(a1), "r"(a2), "r"(a3), "r"(b0), "r"(b1));
}

// ---------------- K1: w1 GEMM via mma.sync + accumulator zeroing ----------------
// D[r, nh] = sum_b comp[r,b] * basis[b,nh].  A = comp (64x32 padded, smem fp16),
// B = basis cols (fp16 from fp32 LDG), fp32 accum, fp16 out.
// Warp owns 32 nh columns (4 n-tiles); block = 4 warps = 128 cols; grid 6250.
__global__ void __launch_bounds__(128) k_w1(const float* __restrict__ basis1,
                                            const float* __restrict__ comp1) {
    __shared__ __align__(16) __half scomp[64 * 32];      // [r(pad64)][b(pad32)]
    __shared__ __align__(16) __half sD[4 * 64 * 40];     // [wid][r(pad64)][nhl(pad40)]

    int tid = threadIdx.x;
    int gid = blockIdx.x * 128 + tid;

    // fold in accumulator zeroing (disjoint arrays; consumed by later launches)
    if (gid < NN * 2 + NN + NN) {
        if (gid < NN * 2) {
            g_xsumh[gid] = make_uint4(0u, 0u, 0u, 0u);
        } else if (gid < NN * 2 + NN) {
            g_osum[gid - NN * 2] = make_float4(0.f, 0.f, 0.f, 0.f);
        } else {
            g_cnt[gid - NN * 3] = 0.f;
        }
    }

    for (int i = tid; i < 64 * 32; i += 128) {
        int r = i >> 5, b = i & 31;
        float c = (r < RR && b < BB) ? comp1[r * BB + b] : 0.f;
        scomp[i] = __float2half(c);
    }
    __syncthreads();

    int wid  = tid >> 5;
    int lane = tid & 31;
    int g    = lane >> 2;
    int t2   = (lane & 3) * 2;

    size_t n0 = ((size_t)blockIdx.x * 4 + wid) * 32;

    // A fragments from smem (once): 4 m-tiles x 2 k-steps x 4 regs
    unsigned int afr[4][2][4];
    const unsigned int* scw = (const unsigned int*)scomp;
    #pragma unroll
    for (int m = 0; m < 4; m++) {
        #pragma unroll
        for (int k = 0; k < 2; k++) {
            int rlo = m * 16 + g, rhi = rlo + 8;
            int bc = k * 16 + t2;
            afr[m][k][0] = scw[(rlo * 32 + bc) >> 1];
            afr[m][k][1] = scw[(rhi * 32 + bc) >> 1];
            afr[m][k][2] = scw[(rlo * 32 + bc + 8) >> 1];
            afr[m][k][3] = scw[(rhi * 32 + bc + 8) >> 1];
        }
    }

    unsigned int* sDw = (unsigned int*)sD;

    #pragma unroll
    for (int j = 0; j < 4; j++) {
        size_t col = n0 + j * 8 + g;
        // B fragments: basis rows t2.., cols col (fp32 -> fp16)
        float f0 = basis1[(size_t)(t2)      * NH + col];
        float f1 = basis1[(size_t)(t2 + 1)  * NH + col];
        float f2 = basis1[(size_t)(t2 + 8)  * NH + col];
        float f3 = basis1[(size_t)(t2 + 9)  * NH + col];
        float f4 = basis1[(size_t)(t2 + 16) * NH + col];
        float f5 = basis1[(size_t)(t2 + 17) * NH + col];
        float f6 = 0.f, f7 = 0.f;
        if (t2 < 6) {  // b = 30,31 are zero padding (would be OOB)
            f6 = basis1[(size_t)(t2 + 24) * NH + col];
            f7 = basis1[(size_t)(t2 + 25) * NH + col];
        }
        unsigned int b00 = h2bits(__floats2half2_rn(f0, f1));
        unsigned int b01 = h2bits(__floats2half2_rn(f2, f3));
        unsigned int b10 = h2bits(__floats2half2_rn(f4, f5));
        unsigned int b11 = h2bits(__floats2half2_rn(f6, f7));

        #pragma unroll
        for (int m = 0; m < 4; m++) {
            float d0 = 0.f, d1 = 0.f, d2 = 0.f, d3 = 0.f;
            mma16816(d0, d1, d2, d3, afr[m][0][0], afr[m][0][1], afr[m][0][2], afr[m][0][3], b00, b01);
            mma16816(d0, d1, d2, d3, afr[m][1][0], afr[m][1][1], afr[m][1][2], afr[m][1][3], b10, b11);
            int rlo = m * 16 + g, rhi = rlo + 8;
            int nhl = j * 8 + t2;
            sDw[((wid * 64 + rlo) * 40 + nhl) >> 1] = h2bits(__floats2half2_rn(d0, d1));
            sDw[((wid * 64 + rhi) * 40 + nhl) >> 1] = h2bits(__floats2half2_rn(d2, d3));
        }
    }
    __syncwarp();

    // coalesced store: 50 rows x 32 halves per warp
    #pragma unroll
    for (int jj = 0; jj < 7; jj++) {
        int u = jj * 32 + lane;
        int r = u >> 2, cu = u & 3;
        if (r < RR) {
            uint4 v = *(const uint4*)&sD[(wid * 64 + r) * 40 + cu * 8];
            *(uint4*)((__half*)g_w1h + (size_t)r * NH + n0 + cu * 8) = v;
        }
    }
}

// ---------------- K2: layer-1 edge pass (LTS-atomic floor) ----------------
__global__ void k_edge1(const int* __restrict__ ei, const int* __restrict__ et) {
    int e = blockIdx.x * blockDim.x + threadIdx.x;
    if (e >= EE) return;
    int s = ei[e];
    int d = ei[EE + e];
    int t = et[e];
    const uint4* row = g_w1h + ((size_t)t * NN + s) * 2;
    uint4 a = row[0], b = row[1];
    uint4* dst = g_xsumh + d * 2;
    red4h(dst + 0, a);
    red4h(dst + 1, b);
    red1(&g_cnt[d], 1.0f);
}

// ---------------- K3: x = relu(mean + root1 + bias1), plus transposed fp16 w2 build ----------------
__global__ void k_x_w2(const float4* __restrict__ root1, const float4* __restrict__ bias1,
                       const float* __restrict__ comp2, const float* __restrict__ basis2) {
    if (blockIdx.x == NBLKN) {
        __shared__ float sc[RR * BB];
        __shared__ float sb[BB * HH * CC];
        for (int i = threadIdx.x; i < RR * BB; i += blockDim.x) sc[i] = comp2[i];
        for (int i = threadIdx.x; i < BB * HH * CC; i += blockDim.x) sb[i] = basis2[i];
        __syncthreads();
        __half* w2p = (__half*)g_w2t;
        for (int i = threadIdx.x; i < RR * HH * CC; i += blockDim.x) {
            int r = i / (HH * CC);
            int hc = i % (HH * CC);
            int h = hc / CC, c = hc % CC;
            float acc = 0.f;
            #pragma unroll
            for (int b = 0; b < BB; b++) acc += sc[r * BB + b] * sb[b * HH * CC + hc];
            w2p[r * 64 + c * 16 + h] = __float2half(acc);   // transposed [t][c][h]
        }
        return;
    }

    int n = blockIdx.x * blockDim.x + threadIdx.x;
    if (n >= NN) return;
    float inv = 1.f / fmaxf(g_cnt[n], 1.f);
    uint4 a = g_xsumh[n * 2];
    uint4 b = g_xsumh[n * 2 + 1];
    unsigned int w[8] = {a.x, a.y, a.z, a.w, b.x, b.y, b.z, b.w};
    unsigned int hx[8];
    #pragma unroll
    for (int j = 0; j < 4; j++) {
        float2 lo = __half22float2(bits2h(w[j * 2]));
        float2 hi = __half22float2(bits2h(w[j * 2 + 1]));
        float4 rv = root1[n * 4 + j];
        float4 bv = bias1[j];
        float4 o;
        o.x = fmaxf(lo.x * inv + rv.x + bv.x, 0.f);
        o.y = fmaxf(lo.y * inv + rv.y + bv.y, 0.f);
        o.z = fmaxf(hi.x * inv + rv.z + bv.z, 0.f);
        o.w = fmaxf(hi.y * inv + rv.w + bv.w, 0.f);
        g_x[n * 4 + j] = o;
        hx[j * 2]     = h2bits(__floats2half2_rn(o.x, o.y));
        hx[j * 2 + 1] = h2bits(__floats2half2_rn(o.z, o.w));
    }
    g_xh[n * 2]     = make_uint4(hx[0], hx[1], hx[2], hx[3]);
    g_xh[n * 2 + 1] = make_uint4(hx[4], hx[5], hx[6], hx[7]);
}

// ---------------- K4: layer-2, 4 lanes per edge, no shuffles ----------------
__global__ void k_edge2(const int* __restrict__ ei, const int* __restrict__ et) {
    int gt = blockIdx.x * blockDim.x + threadIdx.x;
    int e   = gt >> 2;
    int sub = gt & 3;
    if (e >= EE) return;
    int s = ei[e];
    int d = ei[EE + e];
    int t = et[e];

    const uint4* xr = g_xh + (size_t)s * 2;
    uint4 xa = xr[0], xb = xr[1];
    const uint4* wr = g_w2t + t * 8 + sub * 2;
    uint4 w0 = wr[0], w1 = wr[1];

    float acc = 0.f;
    {
        float2 xf, wf;
        xf = __half22float2(bits2h(xa.x)); wf = __half22float2(bits2h(w0.x));
        acc = fmaf(xf.x, wf.x, fmaf(xf.y, wf.y, acc));
        xf = __half22float2(bits2h(xa.y)); wf = __half22float2(bits2h(w0.y));
        acc = fmaf(xf.x, wf.x, fmaf(xf.y, wf.y, acc));
        xf = __half22float2(bits2h(xa.z)); wf = __half22float2(bits2h(w0.z));
        acc = fmaf(xf.x, wf.x, fmaf(xf.y, wf.y, acc));
        xf = __half22float2(bits2h(xa.w)); wf = __half22float2(bits2h(w0.w));
        acc = fmaf(xf.x, wf.x, fmaf(xf.y, wf.y, acc));
        xf = __half22float2(bits2h(xb.x)); wf = __half22float2(bits2h(w1.x));
        acc = fmaf(xf.x, wf.x, fmaf(xf.y, wf.y, acc));
        xf = __half22float2(bits2h(xb.y)); wf = __half22float2(bits2h(w1.y));
        acc = fmaf(xf.x, wf.x, fmaf(xf.y, wf.y, acc));
        xf = __half22float2(bits2h(xb.z)); wf = __half22float2(bits2h(w1.z));
        acc = fmaf(xf.x, wf.x, fmaf(xf.y, wf.y, acc));
        xf = __half22float2(bits2h(xb.w)); wf = __half22float2(bits2h(w1.w));
        acc = fmaf(xf.x, wf.x, fmaf(xf.y, wf.y, acc));
    }

    red1((float*)g_osum + (size_t)d * 4 + sub, acc);
}

// ---------------- K5: out = log_softmax(osum/max(cnt,1) + x @ root2 + bias2) ----------------
__global__ void k_out(const float4* __restrict__ root2, const float4* __restrict__ bias2,
                      float4* __restrict__ out) {
    __shared__ float4 sr2[HH];
    __shared__ float4 sb2;
    if (threadIdx.x < HH) sr2[threadIdx.x] = root2[threadIdx.x];
    if (threadIdx.x == 0) sb2 = bias2[0];
    __syncthreads();

    int n = blockIdx.x * blockDim.x + threadIdx.x;
    if (n >= NN) return;

    float inv = 1.f / fmaxf(g_cnt[n], 1.f);
    float4 os = g_osum[n];
    float4 acc;
    acc.x = os.x * inv + sb2.x;
    acc.y = os.y * inv + sb2.y;
    acc.z = os.z * inv + sb2.z;
    acc.w = os.w * inv + sb2.w;

    const float4* xr = g_x + n * 4;
    #pragma unroll
    for (int j = 0; j < 4; j++) {
        float4 xv = xr[j];
        fma4(acc, xv.x, sr2[j * 4 + 0]);
        fma4(acc, xv.y, sr2[j * 4 + 1]);
        fma4(acc, xv.z, sr2[j * 4 + 2]);
        fma4(acc, xv.w, sr2[j * 4 + 3]);
    }

    float m = fmaxf(fmaxf(acc.x, acc.y), fmaxf(acc.z, acc.w));
    float se = expf(acc.x - m) + expf(acc.y - m) + expf(acc.z - m) + expf(acc.w - m);
    float l = m + logf(se);
    float4 o;
    o.x = acc.x - l; o.y = acc.y - l; o.z = acc.z - l; o.w = acc.w - l;
    out[n] = o;
}

// ---------------- launcher (5 graph nodes) ----------------
extern "C" void kernel_launch(void* const* d_in, const int* in_sizes, int n_in,
                              void* d_out, int out_size) {
    const int*    ei        = (const int*)d_in[0];         // edge_index [2,E] int32
    const int*    et        = (const int*)d_in[1];         // edge_type  [E]   int32
    // d_in[2] edge_norm: unused by the reference forward
    const float*  basis1    = (const float*)d_in[3];       // [B,N,H]
    const float*  comp1     = (const float*)d_in[4];       // [R,B]
    const float4* root1     = (const float4*)d_in[5];      // [N,H]
    const float4* bias1     = (const float4*)d_in[6];      // [H]
    const float*  basis2    = (const float*)d_in[7];       // [B,H,C]
    const float*  comp2     = (const float*)d_in[8];       // [R,B]
    const float4* root2     = (const float4*)d_in[9];      // [H,C]
    const float4* bias2     = (const float4*)d_in[10];     // [C]
    float4* out = (float4*)d_out;

    (void)in_sizes; (void)n_in; (void)out_size;

    k_w1   <<<NH / 128, 128>>>(basis1, comp1);   // 6250 blocks x 4 warps x 32 cols
    k_edge1<<<(EE + 255) / 256, 256>>>(ei, et);
    k_x_w2 <<<NBLKN + 1, 256>>>(root1, bias1, comp2, basis2);
    k_edge2<<<(EE * 4 + 255) / 256, 256>>>(ei, et);
    k_out  <<<(NN + 255) / 256, 256>>>(root2, bias2, out);
}